// round 1
// baseline (speedup 1.0000x reference)
#include <cuda_runtime.h>

// ---------------------------------------------------------------------------
// LocalSimilarity: B=8, N=32, C=768, P=16, T=256, K=5
// Pipeline: norms -> per-(b,n) 256x256x768 fp32 sim GEMM + fused argmax/
// masking/cycle-consistency -> per-batch top-5 + output formatting.
// ---------------------------------------------------------------------------

#define B_      8
#define N_      32
#define C_      768
#define T_      256
#define K_TOP   5
#define SIM_THR 0.05f

#define KC 16   // k-chunk
#define RB 64   // row block (target patches per pass)

// Scratch (device globals: no allocations allowed)
__device__ float g_invs[B_ * N_ * T_];
__device__ float g_invt[B_ * T_];
__device__ float g_maskall[B_ * N_ * T_];
__device__ float g_scoret[B_ * N_ * T_];
__device__ int   g_idxt[B_ * N_ * T_];
__device__ float g_avg[B_ * N_];
__device__ float g_mc[B_ * N_];

// ---------------------------------------------------------------------------
// Kernel 1: inverse L2 norms over channel dim for src (B,N,T) and tar (B,T)
// ---------------------------------------------------------------------------
__global__ void norms_kernel(const float* __restrict__ sf,
                             const float* __restrict__ tf) {
    int blk = blockIdx.x;
    int t = threadIdx.x;
    if (blk < B_ * N_) {
        const float* p = sf + (size_t)blk * C_ * T_ + t;
        float ss = 0.f;
#pragma unroll 8
        for (int c = 0; c < C_; c++) {
            float v = p[(size_t)c * T_];
            ss = fmaf(v, v, ss);
        }
        g_invs[blk * T_ + t] = 1.f / fmaxf(sqrtf(ss), 1e-12f);
    } else {
        int b = blk - B_ * N_;
        const float* p = tf + (size_t)b * C_ * T_ + t;
        float ss = 0.f;
#pragma unroll 8
        for (int c = 0; c < C_; c++) {
            float v = p[(size_t)c * T_];
            ss = fmaf(v, v, ss);
        }
        g_invt[b * T_ + t] = 1.f / fmaxf(sqrtf(ss), 1e-12f);
    }
}

// ---------------------------------------------------------------------------
// Kernel 2: per-(b,n) dense similarity + dual NN + cycle consistency
// One CTA per (b,n). 256 threads. 4 row-blocks of 64 rows x 256 cols.
// Thread tile: 8 rows x (4+4) cols. KC=16 smem k-chunks.
// ---------------------------------------------------------------------------
__global__ __launch_bounds__(256, 2)
void sim_kernel(const float* __restrict__ sf, const float* __restrict__ tf,
                const float* __restrict__ srcm, const float* __restrict__ tarm) {
    __shared__ float As[KC][RB];            // tf chunk: k-major (rows = t)
    __shared__ float Bs[KC][T_];            // sf chunk: k-major (cols = s)
    __shared__ unsigned long long colmax[T_];
    __shared__ float row_score[T_];
    __shared__ int   row_idx[T_];
    __shared__ float wsum1[8], wsum2[8];

    const int tid = threadIdx.x;
    const int tx = tid & 31;
    const int ty = tid >> 5;               // warp id 0..7
    const int bn = blockIdx.x;
    const int b  = bn >> 5;

    const float* sfp = sf + (size_t)bn * C_ * T_;
    const float* tfp = tf + (size_t)b  * C_ * T_;

    const int c0 = tx * 4;                 // cols c0..c0+3
    const int c1 = 128 + tx * 4;           // cols c1..c1+3

    float invs_r[8], srcm_r[8];
#pragma unroll
    for (int j = 0; j < 4; j++) {
        invs_r[j]     = g_invs[bn * T_ + c0 + j];
        invs_r[j + 4] = g_invs[bn * T_ + c1 + j];
        srcm_r[j]     = srcm[bn * T_ + c0 + j];
        srcm_r[j + 4] = srcm[bn * T_ + c1 + j];
    }

    // colmax init: pack(score=0.0, t=0): high 32 = 0, low 32 = 65535-0
    colmax[tid] = 0xFFFFull;
    __syncthreads();

    for (int rb = 0; rb < T_ / RB; rb++) {
        const int trow0 = rb * RB;
        float acc[8][8];
#pragma unroll
        for (int i = 0; i < 8; i++)
#pragma unroll
            for (int j = 0; j < 8; j++) acc[i][j] = 0.f;

        for (int ck = 0; ck < C_; ck += KC) {
            // Load As: 16 rows x 64 floats = 256 float4 (1/thread)
            {
                int row  = tid >> 4;        // 0..15
                int col4 = tid & 15;        // 0..15
                const float4* gp =
                    (const float4*)(tfp + (size_t)(ck + row) * T_ + trow0) + col4;
                *(float4*)&As[row][col4 * 4] = *gp;
            }
            // Load Bs: 16 rows x 256 floats = 1024 float4 (4/thread)
            {
                int col4 = tid & 63;        // 0..63
#pragma unroll
                for (int i2 = 0; i2 < 4; i2++) {
                    int row = (tid >> 6) + i2 * 4;
                    const float4* gp =
                        (const float4*)(sfp + (size_t)(ck + row) * T_) + col4;
                    *(float4*)&Bs[row][col4 * 4] = *gp;
                }
            }
            __syncthreads();

#pragma unroll
            for (int k = 0; k < KC; k++) {
                float a[8], bb[8];
                float4 a0 = *(const float4*)&As[k][ty * 8];
                float4 a1 = *(const float4*)&As[k][ty * 8 + 4];
                a[0] = a0.x; a[1] = a0.y; a[2] = a0.z; a[3] = a0.w;
                a[4] = a1.x; a[5] = a1.y; a[6] = a1.z; a[7] = a1.w;
                float4 b0 = *(const float4*)&Bs[k][c0];
                float4 b1 = *(const float4*)&Bs[k][c1];
                bb[0] = b0.x; bb[1] = b0.y; bb[2] = b0.z; bb[3] = b0.w;
                bb[4] = b1.x; bb[5] = b1.y; bb[6] = b1.z; bb[7] = b1.w;
#pragma unroll
                for (int i = 0; i < 8; i++)
#pragma unroll
                    for (int j = 0; j < 8; j++)
                        acc[i][j] = fmaf(a[i], bb[j], acc[i][j]);
            }
            __syncthreads();
        }

        // ---- epilogue for this row block: mask, threshold, row/col argmax ----
#pragma unroll
        for (int i = 0; i < 8; i++) {
            int r = trow0 + ty * 8 + i;
            float rs = g_invt[b * T_ + r] * tarm[b * T_ + r];
            float bv = -1.f; int bc = 0;
#pragma unroll
            for (int j = 0; j < 8; j++) {
                int c = (j < 4) ? (c0 + j) : (c1 + j - 4);
                float v = acc[i][j] * rs * invs_r[j] * srcm_r[j];
                if (v < SIM_THR) v = 0.f;
                acc[i][j] = v;
                if (v > bv) { bv = v; bc = c; }
            }
            // warp reduce: max score, tie -> smaller col (matches first-argmax)
#pragma unroll
            for (int off = 16; off; off >>= 1) {
                float ov = __shfl_xor_sync(0xffffffffu, bv, off);
                int   oc = __shfl_xor_sync(0xffffffffu, bc, off);
                if (ov > bv || (ov == bv && oc < bc)) { bv = ov; bc = oc; }
            }
            if (tx == 0) { row_score[r] = bv; row_idx[r] = bc; }
        }
        // column maxima: local over 8 rows (ascending -> tie keeps smaller t),
        // then packed 64-bit shared atomicMax (tie -> smaller t via 65535-t)
#pragma unroll
        for (int j = 0; j < 8; j++) {
            int c = (j < 4) ? (c0 + j) : (c1 + j - 4);
            float bv = -1.f; int br = 0;
#pragma unroll
            for (int i = 0; i < 8; i++) {
                if (acc[i][j] > bv) { bv = acc[i][j]; br = trow0 + ty * 8 + i; }
            }
            unsigned long long key =
                ((unsigned long long)__float_as_uint(bv) << 32) |
                (unsigned)(65535 - br);
            atomicMax(&colmax[c], key);
        }
        __syncthreads();
    }

    // ---- post phase: cycle consistency + masks, one thread per t ----
    {
        int t = tid;
        float st = row_score[t];
        int   it = row_idx[t];
        unsigned long long cm_t  = colmax[t];
        unsigned long long cm_it = colmax[it];
        int idx_s2t_t = 65535 - (int)(unsigned)(cm_t & 0xFFFFFFFFull);
        float sc_s2t  = __uint_as_float((unsigned)(cm_it >> 32));
        int idx_s2s   = 65535 - (int)(unsigned)(cm_it & 0xFFFFFFFFull);

        bool msim = (st >= SIM_THR);
        int dx = (idx_s2s & 15) - (t & 15);
        int dy = (idx_s2s >> 4) - (t >> 4);
        bool mcyc = (dx * dx + dy * dy <= 4) && (sc_s2t >= SIM_THR);

        float mall = 0.f;
        if (msim && mcyc) {
            float mt2s = srcm[bn * T_ + it];
            float tm   = tarm[b * T_ + t];
            mall = tm * mt2s * ((idx_s2t_t != 0) ? 1.f : 0.f)
                             * ((it != 0) ? 1.f : 0.f);
        }
        g_maskall[bn * T_ + t] = mall;
        g_scoret[bn * T_ + t]  = st;
        g_idxt[bn * T_ + t]    = it;

        float s1 = mall, s2 = st * mall;
#pragma unroll
        for (int off = 16; off; off >>= 1) {
            s1 += __shfl_xor_sync(0xffffffffu, s1, off);
            s2 += __shfl_xor_sync(0xffffffffu, s2, off);
        }
        if (tx == 0) { wsum1[ty] = s1; wsum2[ty] = s2; }
        __syncthreads();
        if (tid == 0) {
            float mc = 0.f, ss = 0.f;
            for (int w = 0; w < 8; w++) { mc += wsum1[w]; ss += wsum2[w]; }
            g_mc[bn]  = mc;
            g_avg[bn] = (mc > 0.f) ? ss / (float)T_ : 0.f;
        }
    }
}

// ---------------------------------------------------------------------------
// Kernel 3: per-batch top-5 (stable: lower index on ties) + output formatting
// Output (float32, concatenated in reference return order):
//   id_src (B,K)=40 | score_src 40 | score_pts (B,K,T)=10240 |
//   tar_pts (B,K,T,2)=20480 | src_pts 20480 | match_counts (B,N)=256
// ---------------------------------------------------------------------------
__global__ void finalize_kernel(float* __restrict__ out) {
    int b = blockIdx.x;
    int tid = threadIdx.x;
    __shared__ int   sid[K_TOP];
    __shared__ float sval[K_TOP];

    if (tid == 0) {
        bool used[N_];
        for (int n = 0; n < N_; n++) used[n] = false;
        for (int k = 0; k < K_TOP; k++) {
            float best = -1.f; int bi = 0; bool found = false;
            for (int n = 0; n < N_; n++) {
                float v = g_avg[b * N_ + n];
                if (!used[n] && (!found || v > best)) {
                    best = v; bi = n; found = true;
                }
            }
            used[bi] = true; sid[k] = bi; sval[k] = best;
        }
    }
    __syncthreads();

    if (tid < K_TOP) {
        out[b * K_TOP + tid] = (float)sid[tid];
        out[B_ * K_TOP + b * K_TOP + tid] = sval[tid];
    }

    const int OFF_SP   = 2 * B_ * K_TOP;                 // 80
    const int OFF_TP   = OFF_SP + B_ * K_TOP * T_;       // 10320
    const int OFF_SRCP = OFF_TP + B_ * K_TOP * T_ * 2;   // 30800
    const int OFF_MC   = OFF_SRCP + B_ * K_TOP * T_ * 2; // 51280

    int t = tid;
#pragma unroll
    for (int k = 0; k < K_TOP; k++) {
        int bnsel = b * N_ + sid[k];
        float sc = g_scoret[bnsel * T_ + t];
        float m  = g_maskall[bnsel * T_ + t];
        int   it = g_idxt[bnsel * T_ + t];
        int base = (b * K_TOP + k) * T_ + t;
        out[OFF_SP + base] = sc;
        bool nz = (m != 0.f);
        out[OFF_TP + base * 2 + 0]   = nz ? (float)(t & 15)  : -1.f;
        out[OFF_TP + base * 2 + 1]   = nz ? (float)(t >> 4)  : -1.f;
        out[OFF_SRCP + base * 2 + 0] = nz ? (float)(it & 15) : -1.f;
        out[OFF_SRCP + base * 2 + 1] = nz ? (float)(it >> 4) : -1.f;
    }
    if (tid < N_) out[OFF_MC + b * N_ + tid] = g_mc[b * N_ + tid];
}

// ---------------------------------------------------------------------------
extern "C" void kernel_launch(void* const* d_in, const int* in_sizes, int n_in,
                              void* d_out, int out_size) {
    const float* sf   = (const float*)d_in[0];  // (B,N,C,P,P)
    const float* tf   = (const float*)d_in[1];  // (B,C,P,P)
    const float* srcm = (const float*)d_in[2];  // (B,N,P,P)
    const float* tarm = (const float*)d_in[3];  // (B,P,P)

    norms_kernel<<<B_ * N_ + B_, 256>>>(sf, tf);
    sim_kernel<<<B_ * N_, 256>>>(sf, tf, srcm, tarm);
    finalize_kernel<<<B_, 256>>>((float*)d_out);
}

// round 2
// speedup vs baseline: 1.0391x; 1.0391x over previous
#include <cuda_runtime.h>

// ---------------------------------------------------------------------------
// LocalSimilarity: B=8, N=32, C=768, P=16, T=256, K=5
// R2: packed fma.rn.f32x2 inner loop (duplicated-A smem for mov-free packed
// broadcast operands) + 4-way-split norms kernel for higher MLP.
// ---------------------------------------------------------------------------

#define B_      8
#define N_      32
#define C_      768
#define T_      256
#define K_TOP   5
#define SIM_THR 0.05f

#define KC 16   // k-chunk
#define RB 64   // row block (target patches per pass)
#define NCHUNK 4
#define CPC (C_ / NCHUNK)   // 192 channels per norms chunk

// Scratch (device globals: no allocations allowed)
__device__ float g_part[NCHUNK][(B_ * N_ + B_) * T_];
__device__ float g_invs[B_ * N_ * T_];
__device__ float g_invt[B_ * T_];
__device__ float g_maskall[B_ * N_ * T_];
__device__ float g_scoret[B_ * N_ * T_];
__device__ int   g_idxt[B_ * N_ * T_];
__device__ float g_avg[B_ * N_];
__device__ float g_mc[B_ * N_];

// ---------------------------------------------------------------------------
// Kernel 1a: partial sum-of-squares over a 192-channel chunk
// grid (B*N + B, NCHUNK), 256 threads
// ---------------------------------------------------------------------------
__global__ void norms_partial_kernel(const float* __restrict__ sf,
                                     const float* __restrict__ tf) {
    int blk = blockIdx.x;
    int ch  = blockIdx.y;
    int t = threadIdx.x;
    const float* p;
    if (blk < B_ * N_) {
        p = sf + (size_t)blk * C_ * T_ + (size_t)ch * CPC * T_ + t;
    } else {
        p = tf + (size_t)(blk - B_ * N_) * C_ * T_ + (size_t)ch * CPC * T_ + t;
    }
    float ss = 0.f;
#pragma unroll 16
    for (int c = 0; c < CPC; c++) {
        float v = p[(size_t)c * T_];
        ss = fmaf(v, v, ss);
    }
    g_part[ch][blk * T_ + t] = ss;
}

// Kernel 1b: combine partials -> inverse norms
__global__ void norms_combine_kernel() {
    int blk = blockIdx.x;
    int t = threadIdx.x;
    int i = blk * T_ + t;
    float ss = g_part[0][i] + g_part[1][i] + g_part[2][i] + g_part[3][i];
    float inv = 1.f / fmaxf(sqrtf(ss), 1e-12f);
    if (blk < B_ * N_) g_invs[i] = inv;
    else               g_invt[(blk - B_ * N_) * T_ + t] = inv;
}

// ---------------------------------------------------------------------------
// Kernel 2: per-(b,n) dense similarity + dual NN + cycle consistency
// One CTA per (b,n). 256 threads. 4 row-blocks of 64 rows x 256 cols.
// Thread tile: 8 rows x 8 cols as 8x4 packed-f32x2 accumulators.
// ---------------------------------------------------------------------------
__global__ __launch_bounds__(256, 2)
void sim_kernel(const float* __restrict__ sf, const float* __restrict__ tf,
                const float* __restrict__ srcm, const float* __restrict__ tarm) {
    __shared__ float As2[KC][RB * 2];       // tf chunk, DUPLICATED: a,a,b,b,...
    __shared__ float Bs[KC][T_];            // sf chunk: k-major (cols = s)
    __shared__ unsigned long long colmax[T_];
    __shared__ float row_score[T_];
    __shared__ int   row_idx[T_];
    __shared__ float wsum1[8], wsum2[8];

    const int tid = threadIdx.x;
    const int tx = tid & 31;
    const int ty = tid >> 5;               // warp id 0..7
    const int bn = blockIdx.x;
    const int b  = bn >> 5;

    const float* sfp = sf + (size_t)bn * C_ * T_;
    const float* tfp = tf + (size_t)b  * C_ * T_;

    const int c0 = tx * 4;                 // cols c0..c0+3
    const int c1 = 128 + tx * 4;           // cols c1..c1+3

    float invs_r[8], srcm_r[8];
#pragma unroll
    for (int j = 0; j < 4; j++) {
        invs_r[j]     = g_invs[bn * T_ + c0 + j];
        invs_r[j + 4] = g_invs[bn * T_ + c1 + j];
        srcm_r[j]     = srcm[bn * T_ + c0 + j];
        srcm_r[j + 4] = srcm[bn * T_ + c1 + j];
    }

    // shared-space base addresses for asm loads
    const unsigned sa_base = (unsigned)__cvta_generic_to_shared(&As2[0][ty * 16]);
    const unsigned sb0_base = (unsigned)__cvta_generic_to_shared(&Bs[0][c0]);
    const unsigned sb1_base = (unsigned)__cvta_generic_to_shared(&Bs[0][c1]);

    // colmax init: pack(score=0.0, t=0): high 32 = 0, low 32 = 65535-0
    colmax[tid] = 0xFFFFull;
    __syncthreads();

    for (int rb = 0; rb < T_ / RB; rb++) {
        const int trow0 = rb * RB;
        unsigned long long acc2[8][4];
#pragma unroll
        for (int i = 0; i < 8; i++)
#pragma unroll
            for (int j = 0; j < 4; j++) acc2[i][j] = 0ull;

        for (int ck = 0; ck < C_; ck += KC) {
            // Load As2 duplicated: 16 rows x 64 src floats (1 float4/thread,
            // stored twice with element duplication)
            {
                int row  = tid >> 4;        // 0..15
                int col4 = tid & 15;        // 0..15
                const float4* gp =
                    (const float4*)(tfp + (size_t)(ck + row) * T_ + trow0) + col4;
                float4 v = *gp;
                float4 d0 = make_float4(v.x, v.x, v.y, v.y);
                float4 d1 = make_float4(v.z, v.z, v.w, v.w);
                *(float4*)&As2[row][col4 * 8]     = d0;
                *(float4*)&As2[row][col4 * 8 + 4] = d1;
            }
            // Load Bs: 16 rows x 256 floats = 1024 float4 (4/thread)
            {
                int col4 = tid & 63;        // 0..63
#pragma unroll
                for (int i2 = 0; i2 < 4; i2++) {
                    int row = (tid >> 6) + i2 * 4;
                    const float4* gp =
                        (const float4*)(sfp + (size_t)(ck + row) * T_) + col4;
                    *(float4*)&Bs[row][col4 * 4] = *gp;
                }
            }
            __syncthreads();

#pragma unroll
            for (int k = 0; k < KC; k++) {
                unsigned long long a2[8], b2[4];
                // a2[i] = {a_i, a_i} directly from duplicated tile (warp-uniform)
                asm volatile("ld.shared.v2.b64 {%0,%1}, [%2];"
                    : "=l"(a2[0]), "=l"(a2[1]) : "r"(sa_base + k * (RB * 8)));
                asm volatile("ld.shared.v2.b64 {%0,%1}, [%2];"
                    : "=l"(a2[2]), "=l"(a2[3]) : "r"(sa_base + k * (RB * 8) + 16));
                asm volatile("ld.shared.v2.b64 {%0,%1}, [%2];"
                    : "=l"(a2[4]), "=l"(a2[5]) : "r"(sa_base + k * (RB * 8) + 32));
                asm volatile("ld.shared.v2.b64 {%0,%1}, [%2];"
                    : "=l"(a2[6]), "=l"(a2[7]) : "r"(sa_base + k * (RB * 8) + 48));
                // b2[j2] = {col2j2, col2j2+1}
                asm volatile("ld.shared.v2.b64 {%0,%1}, [%2];"
                    : "=l"(b2[0]), "=l"(b2[1]) : "r"(sb0_base + k * (T_ * 4)));
                asm volatile("ld.shared.v2.b64 {%0,%1}, [%2];"
                    : "=l"(b2[2]), "=l"(b2[3]) : "r"(sb1_base + k * (T_ * 4)));
#pragma unroll
                for (int i = 0; i < 8; i++)
#pragma unroll
                    for (int j = 0; j < 4; j++)
                        asm volatile("fma.rn.f32x2 %0, %1, %2, %0;"
                            : "+l"(acc2[i][j]) : "l"(a2[i]), "l"(b2[j]));
            }
            __syncthreads();
        }

        // unpack accumulators
        float acc[8][8];
#pragma unroll
        for (int i = 0; i < 8; i++)
#pragma unroll
            for (int j = 0; j < 4; j++) {
                acc[i][j * 2]     = __uint_as_float((unsigned)(acc2[i][j]));
                acc[i][j * 2 + 1] = __uint_as_float((unsigned)(acc2[i][j] >> 32));
            }

        // ---- epilogue for this row block: mask, threshold, row/col argmax ----
#pragma unroll
        for (int i = 0; i < 8; i++) {
            int r = trow0 + ty * 8 + i;
            float rs = g_invt[b * T_ + r] * tarm[b * T_ + r];
            float bv = -1.f; int bc = 0;
#pragma unroll
            for (int j = 0; j < 8; j++) {
                int c = (j < 4) ? (c0 + j) : (c1 + j - 4);
                float v = acc[i][j] * rs * invs_r[j] * srcm_r[j];
                if (v < SIM_THR) v = 0.f;
                acc[i][j] = v;
                if (v > bv) { bv = v; bc = c; }
            }
            // warp reduce: max score, tie -> smaller col (matches first-argmax)
#pragma unroll
            for (int off = 16; off; off >>= 1) {
                float ov = __shfl_xor_sync(0xffffffffu, bv, off);
                int   oc = __shfl_xor_sync(0xffffffffu, bc, off);
                if (ov > bv || (ov == bv && oc < bc)) { bv = ov; bc = oc; }
            }
            if (tx == 0) { row_score[r] = bv; row_idx[r] = bc; }
        }
        // column maxima: local over 8 rows (ascending -> tie keeps smaller t),
        // then packed 64-bit shared atomicMax (tie -> smaller t via 65535-t)
#pragma unroll
        for (int j = 0; j < 8; j++) {
            int c = (j < 4) ? (c0 + j) : (c1 + j - 4);
            float bv = -1.f; int br = 0;
#pragma unroll
            for (int i = 0; i < 8; i++) {
                if (acc[i][j] > bv) { bv = acc[i][j]; br = trow0 + ty * 8 + i; }
            }
            unsigned long long key =
                ((unsigned long long)__float_as_uint(bv) << 32) |
                (unsigned)(65535 - br);
            atomicMax(&colmax[c], key);
        }
        __syncthreads();
    }

    // ---- post phase: cycle consistency + masks, one thread per t ----
    {
        int t = tid;
        float st = row_score[t];
        int   it = row_idx[t];
        unsigned long long cm_t  = colmax[t];
        unsigned long long cm_it = colmax[it];
        int idx_s2t_t = 65535 - (int)(unsigned)(cm_t & 0xFFFFFFFFull);
        float sc_s2t  = __uint_as_float((unsigned)(cm_it >> 32));
        int idx_s2s   = 65535 - (int)(unsigned)(cm_it & 0xFFFFFFFFull);

        bool msim = (st >= SIM_THR);
        int dx = (idx_s2s & 15) - (t & 15);
        int dy = (idx_s2s >> 4) - (t >> 4);
        bool mcyc = (dx * dx + dy * dy <= 4) && (sc_s2t >= SIM_THR);

        float mall = 0.f;
        if (msim && mcyc) {
            float mt2s = srcm[bn * T_ + it];
            float tm   = tarm[b * T_ + t];
            mall = tm * mt2s * ((idx_s2t_t != 0) ? 1.f : 0.f)
                             * ((it != 0) ? 1.f : 0.f);
        }
        g_maskall[bn * T_ + t] = mall;
        g_scoret[bn * T_ + t]  = st;
        g_idxt[bn * T_ + t]    = it;

        float s1 = mall, s2 = st * mall;
#pragma unroll
        for (int off = 16; off; off >>= 1) {
            s1 += __shfl_xor_sync(0xffffffffu, s1, off);
            s2 += __shfl_xor_sync(0xffffffffu, s2, off);
        }
        if (tx == 0) { wsum1[ty] = s1; wsum2[ty] = s2; }
        __syncthreads();
        if (tid == 0) {
            float mc = 0.f, ss = 0.f;
            for (int w = 0; w < 8; w++) { mc += wsum1[w]; ss += wsum2[w]; }
            g_mc[bn]  = mc;
            g_avg[bn] = (mc > 0.f) ? ss / (float)T_ : 0.f;
        }
    }
}

// ---------------------------------------------------------------------------
// Kernel 3: per-batch top-5 (stable: lower index on ties) + output formatting
// ---------------------------------------------------------------------------
__global__ void finalize_kernel(float* __restrict__ out) {
    int b = blockIdx.x;
    int tid = threadIdx.x;
    __shared__ int   sid[K_TOP];
    __shared__ float sval[K_TOP];

    if (tid == 0) {
        bool used[N_];
        for (int n = 0; n < N_; n++) used[n] = false;
        for (int k = 0; k < K_TOP; k++) {
            float best = -1.f; int bi = 0; bool found = false;
            for (int n = 0; n < N_; n++) {
                float v = g_avg[b * N_ + n];
                if (!used[n] && (!found || v > best)) {
                    best = v; bi = n; found = true;
                }
            }
            used[bi] = true; sid[k] = bi; sval[k] = best;
        }
    }
    __syncthreads();

    if (tid < K_TOP) {
        out[b * K_TOP + tid] = (float)sid[tid];
        out[B_ * K_TOP + b * K_TOP + tid] = sval[tid];
    }

    const int OFF_SP   = 2 * B_ * K_TOP;                 // 80
    const int OFF_TP   = OFF_SP + B_ * K_TOP * T_;       // 10320
    const int OFF_SRCP = OFF_TP + B_ * K_TOP * T_ * 2;   // 30800
    const int OFF_MC   = OFF_SRCP + B_ * K_TOP * T_ * 2; // 51280

    int t = tid;
#pragma unroll
    for (int k = 0; k < K_TOP; k++) {
        int bnsel = b * N_ + sid[k];
        float sc = g_scoret[bnsel * T_ + t];
        float m  = g_maskall[bnsel * T_ + t];
        int   it = g_idxt[bnsel * T_ + t];
        int base = (b * K_TOP + k) * T_ + t;
        out[OFF_SP + base] = sc;
        bool nz = (m != 0.f);
        out[OFF_TP + base * 2 + 0]   = nz ? (float)(t & 15)  : -1.f;
        out[OFF_TP + base * 2 + 1]   = nz ? (float)(t >> 4)  : -1.f;
        out[OFF_SRCP + base * 2 + 0] = nz ? (float)(it & 15) : -1.f;
        out[OFF_SRCP + base * 2 + 1] = nz ? (float)(it >> 4) : -1.f;
    }
    if (tid < N_) out[OFF_MC + b * N_ + tid] = g_mc[b * N_ + tid];
}

// ---------------------------------------------------------------------------
extern "C" void kernel_launch(void* const* d_in, const int* in_sizes, int n_in,
                              void* d_out, int out_size) {
    const float* sf   = (const float*)d_in[0];  // (B,N,C,P,P)
    const float* tf   = (const float*)d_in[1];  // (B,C,P,P)
    const float* srcm = (const float*)d_in[2];  // (B,N,P,P)
    const float* tarm = (const float*)d_in[3];  // (B,P,P)

    dim3 ng(B_ * N_ + B_, NCHUNK);
    norms_partial_kernel<<<ng, 256>>>(sf, tf);
    norms_combine_kernel<<<B_ * N_ + B_, 256>>>();
    sim_kernel<<<B_ * N_, 256>>>(sf, tf, srcm, tarm);
    finalize_kernel<<<B_, 256>>>((float*)d_out);
}

// round 3
// speedup vs baseline: 1.0404x; 1.0012x over previous
#include <cuda_runtime.h>

// ---------------------------------------------------------------------------
// LocalSimilarity: B=8, N=32, C=768, P=16, T=256, K=5
// R2: packed fma.rn.f32x2 inner loop (duplicated-A smem for mov-free packed
// broadcast operands) + 4-way-split norms kernel for higher MLP.
// ---------------------------------------------------------------------------

#define B_      8
#define N_      32
#define C_      768
#define T_      256
#define K_TOP   5
#define SIM_THR 0.05f

#define KC 16   // k-chunk
#define RB 64   // row block (target patches per pass)
#define NCHUNK 4
#define CPC (C_ / NCHUNK)   // 192 channels per norms chunk

// Scratch (device globals: no allocations allowed)
__device__ float g_part[NCHUNK][(B_ * N_ + B_) * T_];
__device__ float g_invs[B_ * N_ * T_];
__device__ float g_invt[B_ * T_];
__device__ float g_maskall[B_ * N_ * T_];
__device__ float g_scoret[B_ * N_ * T_];
__device__ int   g_idxt[B_ * N_ * T_];
__device__ float g_avg[B_ * N_];
__device__ float g_mc[B_ * N_];

// ---------------------------------------------------------------------------
// Kernel 1a: partial sum-of-squares over a 192-channel chunk
// grid (B*N + B, NCHUNK), 256 threads
// ---------------------------------------------------------------------------
__global__ void norms_partial_kernel(const float* __restrict__ sf,
                                     const float* __restrict__ tf) {
    int blk = blockIdx.x;
    int ch  = blockIdx.y;
    int t = threadIdx.x;
    const float* p;
    if (blk < B_ * N_) {
        p = sf + (size_t)blk * C_ * T_ + (size_t)ch * CPC * T_ + t;
    } else {
        p = tf + (size_t)(blk - B_ * N_) * C_ * T_ + (size_t)ch * CPC * T_ + t;
    }
    float ss = 0.f;
#pragma unroll 16
    for (int c = 0; c < CPC; c++) {
        float v = p[(size_t)c * T_];
        ss = fmaf(v, v, ss);
    }
    g_part[ch][blk * T_ + t] = ss;
}

// Kernel 1b: combine partials -> inverse norms
__global__ void norms_combine_kernel() {
    int blk = blockIdx.x;
    int t = threadIdx.x;
    int i = blk * T_ + t;
    float ss = g_part[0][i] + g_part[1][i] + g_part[2][i] + g_part[3][i];
    float inv = 1.f / fmaxf(sqrtf(ss), 1e-12f);
    if (blk < B_ * N_) g_invs[i] = inv;
    else               g_invt[(blk - B_ * N_) * T_ + t] = inv;
}

// ---------------------------------------------------------------------------
// Kernel 2: per-(b,n) dense similarity + dual NN + cycle consistency
// One CTA per (b,n). 256 threads. 4 row-blocks of 64 rows x 256 cols.
// Thread tile: 8 rows x 8 cols as 8x4 packed-f32x2 accumulators.
// ---------------------------------------------------------------------------
__global__ __launch_bounds__(256, 2)
void sim_kernel(const float* __restrict__ sf, const float* __restrict__ tf,
                const float* __restrict__ srcm, const float* __restrict__ tarm) {
    __shared__ float As2[KC][RB * 2];       // tf chunk, DUPLICATED: a,a,b,b,...
    __shared__ float Bs[KC][T_];            // sf chunk: k-major (cols = s)
    __shared__ unsigned long long colmax[T_];
    __shared__ float row_score[T_];
    __shared__ int   row_idx[T_];
    __shared__ float wsum1[8], wsum2[8];

    const int tid = threadIdx.x;
    const int tx = tid & 31;
    const int ty = tid >> 5;               // warp id 0..7
    const int bn = blockIdx.x;
    const int b  = bn >> 5;

    const float* sfp = sf + (size_t)bn * C_ * T_;
    const float* tfp = tf + (size_t)b  * C_ * T_;

    const int c0 = tx * 4;                 // cols c0..c0+3
    const int c1 = 128 + tx * 4;           // cols c1..c1+3

    float invs_r[8], srcm_r[8];
#pragma unroll
    for (int j = 0; j < 4; j++) {
        invs_r[j]     = g_invs[bn * T_ + c0 + j];
        invs_r[j + 4] = g_invs[bn * T_ + c1 + j];
        srcm_r[j]     = srcm[bn * T_ + c0 + j];
        srcm_r[j + 4] = srcm[bn * T_ + c1 + j];
    }

    // shared-space base addresses for asm loads
    const unsigned sa_base = (unsigned)__cvta_generic_to_shared(&As2[0][ty * 16]);
    const unsigned sb0_base = (unsigned)__cvta_generic_to_shared(&Bs[0][c0]);
    const unsigned sb1_base = (unsigned)__cvta_generic_to_shared(&Bs[0][c1]);

    // colmax init: pack(score=0.0, t=0): high 32 = 0, low 32 = 65535-0
    colmax[tid] = 0xFFFFull;
    __syncthreads();

    for (int rb = 0; rb < T_ / RB; rb++) {
        const int trow0 = rb * RB;
        unsigned long long acc2[8][4];
#pragma unroll
        for (int i = 0; i < 8; i++)
#pragma unroll
            for (int j = 0; j < 4; j++) acc2[i][j] = 0ull;

        for (int ck = 0; ck < C_; ck += KC) {
            // Load As2 duplicated: 16 rows x 64 src floats (1 float4/thread,
            // stored twice with element duplication)
            {
                int row  = tid >> 4;        // 0..15
                int col4 = tid & 15;        // 0..15
                const float4* gp =
                    (const float4*)(tfp + (size_t)(ck + row) * T_ + trow0) + col4;
                float4 v = *gp;
                float4 d0 = make_float4(v.x, v.x, v.y, v.y);
                float4 d1 = make_float4(v.z, v.z, v.w, v.w);
                *(float4*)&As2[row][col4 * 8]     = d0;
                *(float4*)&As2[row][col4 * 8 + 4] = d1;
            }
            // Load Bs: 16 rows x 256 floats = 1024 float4 (4/thread)
            {
                int col4 = tid & 63;        // 0..63
#pragma unroll
                for (int i2 = 0; i2 < 4; i2++) {
                    int row = (tid >> 6) + i2 * 4;
                    const float4* gp =
                        (const float4*)(sfp + (size_t)(ck + row) * T_) + col4;
                    *(float4*)&Bs[row][col4 * 4] = *gp;
                }
            }
            __syncthreads();

#pragma unroll
            for (int k = 0; k < KC; k++) {
                unsigned long long a2[8], b2[4];
                // a2[i] = {a_i, a_i} directly from duplicated tile (warp-uniform)
                asm volatile("ld.shared.v2.b64 {%0,%1}, [%2];"
                    : "=l"(a2[0]), "=l"(a2[1]) : "r"(sa_base + k * (RB * 8)));
                asm volatile("ld.shared.v2.b64 {%0,%1}, [%2];"
                    : "=l"(a2[2]), "=l"(a2[3]) : "r"(sa_base + k * (RB * 8) + 16));
                asm volatile("ld.shared.v2.b64 {%0,%1}, [%2];"
                    : "=l"(a2[4]), "=l"(a2[5]) : "r"(sa_base + k * (RB * 8) + 32));
                asm volatile("ld.shared.v2.b64 {%0,%1}, [%2];"
                    : "=l"(a2[6]), "=l"(a2[7]) : "r"(sa_base + k * (RB * 8) + 48));
                // b2[j2] = {col2j2, col2j2+1}
                asm volatile("ld.shared.v2.b64 {%0,%1}, [%2];"
                    : "=l"(b2[0]), "=l"(b2[1]) : "r"(sb0_base + k * (T_ * 4)));
                asm volatile("ld.shared.v2.b64 {%0,%1}, [%2];"
                    : "=l"(b2[2]), "=l"(b2[3]) : "r"(sb1_base + k * (T_ * 4)));
#pragma unroll
                for (int i = 0; i < 8; i++)
#pragma unroll
                    for (int j = 0; j < 4; j++)
                        asm volatile("fma.rn.f32x2 %0, %1, %2, %0;"
                            : "+l"(acc2[i][j]) : "l"(a2[i]), "l"(b2[j]));
            }
            __syncthreads();
        }

        // unpack accumulators
        float acc[8][8];
#pragma unroll
        for (int i = 0; i < 8; i++)
#pragma unroll
            for (int j = 0; j < 4; j++) {
                acc[i][j * 2]     = __uint_as_float((unsigned)(acc2[i][j]));
                acc[i][j * 2 + 1] = __uint_as_float((unsigned)(acc2[i][j] >> 32));
            }

        // ---- epilogue for this row block: mask, threshold, row/col argmax ----
#pragma unroll
        for (int i = 0; i < 8; i++) {
            int r = trow0 + ty * 8 + i;
            float rs = g_invt[b * T_ + r] * tarm[b * T_ + r];
            float bv = -1.f; int bc = 0;
#pragma unroll
            for (int j = 0; j < 8; j++) {
                int c = (j < 4) ? (c0 + j) : (c1 + j - 4);
                float v = acc[i][j] * rs * invs_r[j] * srcm_r[j];
                if (v < SIM_THR) v = 0.f;
                acc[i][j] = v;
                if (v > bv) { bv = v; bc = c; }
            }
            // warp reduce: max score, tie -> smaller col (matches first-argmax)
#pragma unroll
            for (int off = 16; off; off >>= 1) {
                float ov = __shfl_xor_sync(0xffffffffu, bv, off);
                int   oc = __shfl_xor_sync(0xffffffffu, bc, off);
                if (ov > bv || (ov == bv && oc < bc)) { bv = ov; bc = oc; }
            }
            if (tx == 0) { row_score[r] = bv; row_idx[r] = bc; }
        }
        // column maxima: local over 8 rows (ascending -> tie keeps smaller t),
        // then packed 64-bit shared atomicMax (tie -> smaller t via 65535-t)
#pragma unroll
        for (int j = 0; j < 8; j++) {
            int c = (j < 4) ? (c0 + j) : (c1 + j - 4);
            float bv = -1.f; int br = 0;
#pragma unroll
            for (int i = 0; i < 8; i++) {
                if (acc[i][j] > bv) { bv = acc[i][j]; br = trow0 + ty * 8 + i; }
            }
            unsigned long long key =
                ((unsigned long long)__float_as_uint(bv) << 32) |
                (unsigned)(65535 - br);
            atomicMax(&colmax[c], key);
        }
        __syncthreads();
    }

    // ---- post phase: cycle consistency + masks, one thread per t ----
    {
        int t = tid;
        float st = row_score[t];
        int   it = row_idx[t];
        unsigned long long cm_t  = colmax[t];
        unsigned long long cm_it = colmax[it];
        int idx_s2t_t = 65535 - (int)(unsigned)(cm_t & 0xFFFFFFFFull);
        float sc_s2t  = __uint_as_float((unsigned)(cm_it >> 32));
        int idx_s2s   = 65535 - (int)(unsigned)(cm_it & 0xFFFFFFFFull);

        bool msim = (st >= SIM_THR);
        int dx = (idx_s2s & 15) - (t & 15);
        int dy = (idx_s2s >> 4) - (t >> 4);
        bool mcyc = (dx * dx + dy * dy <= 4) && (sc_s2t >= SIM_THR);

        float mall = 0.f;
        if (msim && mcyc) {
            float mt2s = srcm[bn * T_ + it];
            float tm   = tarm[b * T_ + t];
            mall = tm * mt2s * ((idx_s2t_t != 0) ? 1.f : 0.f)
                             * ((it != 0) ? 1.f : 0.f);
        }
        g_maskall[bn * T_ + t] = mall;
        g_scoret[bn * T_ + t]  = st;
        g_idxt[bn * T_ + t]    = it;

        float s1 = mall, s2 = st * mall;
#pragma unroll
        for (int off = 16; off; off >>= 1) {
            s1 += __shfl_xor_sync(0xffffffffu, s1, off);
            s2 += __shfl_xor_sync(0xffffffffu, s2, off);
        }
        if (tx == 0) { wsum1[ty] = s1; wsum2[ty] = s2; }
        __syncthreads();
        if (tid == 0) {
            float mc = 0.f, ss = 0.f;
            for (int w = 0; w < 8; w++) { mc += wsum1[w]; ss += wsum2[w]; }
            g_mc[bn]  = mc;
            g_avg[bn] = (mc > 0.f) ? ss / (float)T_ : 0.f;
        }
    }
}

// ---------------------------------------------------------------------------
// Kernel 3: per-batch top-5 (stable: lower index on ties) + output formatting
// ---------------------------------------------------------------------------
__global__ void finalize_kernel(float* __restrict__ out) {
    int b = blockIdx.x;
    int tid = threadIdx.x;
    __shared__ int   sid[K_TOP];
    __shared__ float sval[K_TOP];

    if (tid == 0) {
        bool used[N_];
        for (int n = 0; n < N_; n++) used[n] = false;
        for (int k = 0; k < K_TOP; k++) {
            float best = -1.f; int bi = 0; bool found = false;
            for (int n = 0; n < N_; n++) {
                float v = g_avg[b * N_ + n];
                if (!used[n] && (!found || v > best)) {
                    best = v; bi = n; found = true;
                }
            }
            used[bi] = true; sid[k] = bi; sval[k] = best;
        }
    }
    __syncthreads();

    if (tid < K_TOP) {
        out[b * K_TOP + tid] = (float)sid[tid];
        out[B_ * K_TOP + b * K_TOP + tid] = sval[tid];
    }

    const int OFF_SP   = 2 * B_ * K_TOP;                 // 80
    const int OFF_TP   = OFF_SP + B_ * K_TOP * T_;       // 10320
    const int OFF_SRCP = OFF_TP + B_ * K_TOP * T_ * 2;   // 30800
    const int OFF_MC   = OFF_SRCP + B_ * K_TOP * T_ * 2; // 51280

    int t = tid;
#pragma unroll
    for (int k = 0; k < K_TOP; k++) {
        int bnsel = b * N_ + sid[k];
        float sc = g_scoret[bnsel * T_ + t];
        float m  = g_maskall[bnsel * T_ + t];
        int   it = g_idxt[bnsel * T_ + t];
        int base = (b * K_TOP + k) * T_ + t;
        out[OFF_SP + base] = sc;
        bool nz = (m != 0.f);
        out[OFF_TP + base * 2 + 0]   = nz ? (float)(t & 15)  : -1.f;
        out[OFF_TP + base * 2 + 1]   = nz ? (float)(t >> 4)  : -1.f;
        out[OFF_SRCP + base * 2 + 0] = nz ? (float)(it & 15) : -1.f;
        out[OFF_SRCP + base * 2 + 1] = nz ? (float)(it >> 4) : -1.f;
    }
    if (tid < N_) out[OFF_MC + b * N_ + tid] = g_mc[b * N_ + tid];
}

// ---------------------------------------------------------------------------
extern "C" void kernel_launch(void* const* d_in, const int* in_sizes, int n_in,
                              void* d_out, int out_size) {
    const float* sf   = (const float*)d_in[0];  // (B,N,C,P,P)
    const float* tf   = (const float*)d_in[1];  // (B,C,P,P)
    const float* srcm = (const float*)d_in[2];  // (B,N,P,P)
    const float* tarm = (const float*)d_in[3];  // (B,P,P)

    dim3 ng(B_ * N_ + B_, NCHUNK);
    norms_partial_kernel<<<ng, 256>>>(sf, tf);
    norms_combine_kernel<<<B_ * N_ + B_, 256>>>();
    sim_kernel<<<B_ * N_, 256>>>(sf, tf, srcm, tarm);
    finalize_kernel<<<B_, 256>>>((float*)d_out);
}

// round 6
// speedup vs baseline: 1.0447x; 1.0041x over previous
#include <cuda_runtime.h>
#include <cuda_bf16.h>
#include <cstdint>

// ---------------------------------------------------------------------------
// LocalSimilarity: B=8, N=32, C=768, P=16, T=256, K=5
// R6: HMMA (mma.sync) with 6-term triple-bf16 split (h1h1+h1h2+h2h1+h2h2+
// h1h3+h3h1), fp32 accumulate -> fp32-level accuracy (~3e-8 cos rms).
// prep (transpose + 3-way split + norms) -> per-(b,n) warp-tiled HMMA sim
// with fused dual-NN / cycle-consistency epilogue -> finalize.
// ---------------------------------------------------------------------------

#define B_      8
#define N_      32
#define C_      768
#define T_      256
#define K_TOP   5
#define SIM_THR 0.05f

#define KC      32                  // K elements per chunk
#define NCHK    (C_ / KC)           // 24
#define RB      128                 // rows (target patches) per row-block

// smem stage layout (bytes): A1 A2 A3 (128 rows x 64B each), B1 B2 B3 (256 x 64B)
#define AOFF(a) ((a) * 8192)
#define BOFF(bq) (24576 + (bq) * 16384)
#define STAGE_BYTES 73728
#define SMEM_DYN (2 * STAGE_BYTES)

// ---------------- scratch (device globals; no allocation allowed) ----------
__device__ __nv_bfloat16 g_A1[B_ * T_ * C_];
__device__ __nv_bfloat16 g_A2[B_ * T_ * C_];
__device__ __nv_bfloat16 g_A3[B_ * T_ * C_];
__device__ __nv_bfloat16 g_B1[(size_t)B_ * N_ * T_ * C_];
__device__ __nv_bfloat16 g_B2[(size_t)B_ * N_ * T_ * C_];
__device__ __nv_bfloat16 g_B3[(size_t)B_ * N_ * T_ * C_];
__device__ float g_invs[B_ * N_ * T_];
__device__ float g_invt[B_ * T_];
__device__ float g_maskall[B_ * N_ * T_];
__device__ float g_scoret[B_ * N_ * T_];
__device__ int   g_idxt[B_ * N_ * T_];
__device__ float g_avg[B_ * N_];
__device__ float g_mc[B_ * N_];

// ---------------- PTX helpers ----------------------------------------------
#define LDSM_X4(r0, r1, r2, r3, addr) \
    asm volatile("ldmatrix.sync.aligned.m8n8.x4.shared.b16 {%0,%1,%2,%3}, [%4];" \
        : "=r"(r0), "=r"(r1), "=r"(r2), "=r"(r3) : "r"(addr))

#define MMA16816(d, a, b) \
    asm volatile("mma.sync.aligned.m16n8k16.row.col.f32.bf16.bf16.f32 " \
        "{%0,%1,%2,%3}, {%4,%5,%6,%7}, {%8,%9}, {%0,%1,%2,%3};" \
        : "+f"((d)[0]), "+f"((d)[1]), "+f"((d)[2]), "+f"((d)[3]) \
        : "r"((a)[0]), "r"((a)[1]), "r"((a)[2]), "r"((a)[3]), \
          "r"((b)[0]), "r"((b)[1]))

__device__ __forceinline__ void cpa16(uint32_t dst, const void* src) {
    asm volatile("cp.async.cg.shared.global [%0], [%1], 16;"
                 :: "r"(dst), "l"(src) : "memory");
}

__device__ __forceinline__ unsigned pack_bf2(__nv_bfloat16 a, __nv_bfloat16 b) {
    return ((unsigned)__bfloat16_as_ushort(b) << 16) | __bfloat16_as_ushort(a);
}

// ---------------------------------------------------------------------------
// Kernel 1: transpose (C,T)->(T,C), triple-bf16 split, fused inv-norms
// grid (B*N + B, T/32), 256 threads
// ---------------------------------------------------------------------------
__global__ void prep_kernel(const float* __restrict__ sf,
                            const float* __restrict__ tf) {
    __shared__ float tile[32][33];
    const int blk = blockIdx.x;
    const int t0 = blockIdx.y * 32;
    const int tid = threadIdx.x;
    const int row = tid >> 3;
    const int cg = tid & 7;

    const float* src;
    __nv_bfloat16 *d1, *d2, *d3;
    const bool istar = (blk >= B_ * N_);
    if (!istar) {
        src = sf + (size_t)blk * C_ * T_;
        d1 = g_B1 + (size_t)blk * T_ * C_;
        d2 = g_B2 + (size_t)blk * T_ * C_;
        d3 = g_B3 + (size_t)blk * T_ * C_;
    } else {
        int b = blk - B_ * N_;
        src = tf + (size_t)b * C_ * T_;
        d1 = g_A1 + (size_t)b * T_ * C_;
        d2 = g_A2 + (size_t)b * T_ * C_;
        d3 = g_A3 + (size_t)b * T_ * C_;
    }

    float ssq = 0.f;
    for (int c0 = 0; c0 < C_; c0 += 32) {
        float4 v = *(const float4*)(src + (size_t)(c0 + row) * T_ + t0 + cg * 4);
        tile[cg * 4 + 0][row] = v.x;
        tile[cg * 4 + 1][row] = v.y;
        tile[cg * 4 + 2][row] = v.z;
        tile[cg * 4 + 3][row] = v.w;
        __syncthreads();
        __nv_bfloat16 h1[4], h2[4], h3[4];
#pragma unroll
        for (int e = 0; e < 4; e++) {
            float x = tile[row][cg * 4 + e];
            ssq = fmaf(x, x, ssq);
            h1[e] = __float2bfloat16_rn(x);
            float r1 = x - __bfloat162float(h1[e]);
            h2[e] = __float2bfloat16_rn(r1);
            float r2 = r1 - __bfloat162float(h2[e]);
            h3[e] = __float2bfloat16_rn(r2);
        }
        size_t oidx = (size_t)(t0 + row) * C_ + c0 + cg * 4;
        *(uint2*)(d1 + oidx) = make_uint2(pack_bf2(h1[0], h1[1]), pack_bf2(h1[2], h1[3]));
        *(uint2*)(d2 + oidx) = make_uint2(pack_bf2(h2[0], h2[1]), pack_bf2(h2[2], h2[3]));
        *(uint2*)(d3 + oidx) = make_uint2(pack_bf2(h3[0], h3[1]), pack_bf2(h3[2], h3[3]));
        __syncthreads();
    }
#pragma unroll
    for (int off = 1; off < 8; off <<= 1)
        ssq += __shfl_xor_sync(0xffffffffu, ssq, off);
    if (cg == 0) {
        float inv = 1.f / fmaxf(sqrtf(ssq), 1e-12f);
        if (!istar) g_invs[blk * T_ + t0 + row] = inv;
        else        g_invt[(blk - B_ * N_) * T_ + t0 + row] = inv;
    }
}

// ---------------------------------------------------------------------------
// Kernel 2: HMMA sim GEMM (6-term split) + fused dual-NN epilogue
// One CTA per (b,n). 256 threads, warp grid 2(M) x 4(N), warp tile 64x64.
// Row-blocks of 128 target rows; K = 768 in 24 double-buffered chunks of 32.
// Swizzled smem rows: offset(row, g) = row*64 + ((g ^ ((row>>1)&3))*16).
// ---------------------------------------------------------------------------
__global__ __launch_bounds__(256, 1)
void sim_hmma_kernel(const float* __restrict__ srcm,
                     const float* __restrict__ tarm) {
    extern __shared__ __align__(1024) char dsm[];
    __shared__ unsigned long long colmax[T_];
    __shared__ unsigned long long rowmax[T_];
    __shared__ float cs[T_];
    __shared__ float rs[T_];
    __shared__ float wsum1[8], wsum2[8];

    const int tid = threadIdx.x;
    const int w = tid >> 5, l = tid & 31;
    const int wm = w >> 2;          // 0..1  (M position, 64 rows)
    const int wn = w & 3;           // 0..3  (N position, 64 cols)
    const int bn = blockIdx.x, b = bn >> 5;

    const uint32_t smbase = (uint32_t)__cvta_generic_to_shared(dsm);

    colmax[tid] = 0ull;
    rowmax[tid] = 0ull;
    cs[tid] = g_invs[bn * T_ + tid] * srcm[bn * T_ + tid];
    rs[tid] = g_invt[b * T_ + tid] * tarm[b * T_ + tid];
    __syncthreads();

    const char* aArr[3] = {
        (const char*)(g_A1 + (size_t)b * T_ * C_),
        (const char*)(g_A2 + (size_t)b * T_ * C_),
        (const char*)(g_A3 + (size_t)b * T_ * C_) };
    const char* bArr[3] = {
        (const char*)(g_B1 + (size_t)bn * T_ * C_),
        (const char*)(g_B2 + (size_t)bn * T_ * C_),
        (const char*)(g_B3 + (size_t)bn * T_ * C_) };

    // per-lane ldmatrix row offsets (constant across chunks)
    const int m8 = l >> 3, r8 = l & 7;
    const int kaA = m8 >> 1;        // A: matrices 0,1 -> kg+0 ; 2,3 -> kg+1
    const int kaB = m8 & 1;         // B: matrices 0,2 -> kg+0 ; 1,3 -> kg+1
    uint32_t aoff[4]; int sAx[4];
#pragma unroll
    for (int mi = 0; mi < 4; mi++) {
        int rowA = wm * 64 + mi * 16 + (m8 & 1) * 8 + r8;
        aoff[mi] = rowA * 64; sAx[mi] = (rowA >> 1) & 3;
    }
    uint32_t boff[4]; int sBx[4];
#pragma unroll
    for (int nt = 0; nt < 4; nt++) {
        int rowB = wn * 64 + nt * 16 + (m8 >> 1) * 8 + r8;
        boff[nt] = rowB * 64; sBx[nt] = (rowB >> 1) & 3;
    }

    // load-task constants
    const int bRow = tid;                      // B row (all 3 arrays)
    const int sB_ld = (bRow >> 1) & 3;
    const int aRow = tid & 127;                // A row (arrays 0,1 | 2)
    const int sA_ld = (aRow >> 1) & 3;

#define LOADCHUNK(ck, stg) do { \
    uint32_t _sb = smbase + (stg) * STAGE_BYTES; \
    _Pragma("unroll") \
    for (int _q = 0; _q < 3; _q++) { \
        const char* _bp = bArr[_q] + (size_t)bRow * (C_ * 2) + (ck) * 64; \
        uint32_t _bd = _sb + BOFF(_q) + bRow * 64; \
        _Pragma("unroll") \
        for (int _g = 0; _g < 4; _g++) \
            cpa16(_bd + ((_g ^ sB_ld) << 4), _bp + _g * 16); \
    } \
    if (tid < 128) { \
        _Pragma("unroll") \
        for (int _q = 0; _q < 2; _q++) { \
            const char* _ap = aArr[_q] + (size_t)(trow0 + aRow) * (C_ * 2) + (ck) * 64; \
            uint32_t _ad = _sb + AOFF(_q) + aRow * 64; \
            _Pragma("unroll") \
            for (int _g = 0; _g < 4; _g++) \
                cpa16(_ad + ((_g ^ sA_ld) << 4), _ap + _g * 16); \
        } \
    } else { \
        const char* _ap = aArr[2] + (size_t)(trow0 + aRow) * (C_ * 2) + (ck) * 64; \
        uint32_t _ad = _sb + AOFF(2) + aRow * 64; \
        _Pragma("unroll") \
        for (int _g = 0; _g < 4; _g++) \
            cpa16(_ad + ((_g ^ sA_ld) << 4), _ap + _g * 16); \
    } \
} while (0)

    for (int rb = 0; rb < T_ / RB; rb++) {
        const int trow0 = rb * RB;
        float acc[4][8][4];
#pragma unroll
        for (int mi = 0; mi < 4; mi++)
#pragma unroll
            for (int ni = 0; ni < 8; ni++)
#pragma unroll
                for (int e = 0; e < 4; e++) acc[mi][ni][e] = 0.f;

        LOADCHUNK(0, 0);
        asm volatile("cp.async.commit_group;" ::: "memory");

        for (int ck = 0; ck < NCHK; ck++) {
            if (ck + 1 < NCHK) LOADCHUNK(ck + 1, (ck + 1) & 1);
            asm volatile("cp.async.commit_group;" ::: "memory");
            asm volatile("cp.async.wait_group 1;" ::: "memory");
            __syncthreads();

            const uint32_t st = smbase + (ck & 1) * STAGE_BYTES;
#pragma unroll
            for (int step = 0; step < 2; step++) {
                const int kg0 = step * 2;
                // pairs grouped by B array: b0 x {a0,a1,a2}, b1 x {a0,a1}, b2 x {a0}
#pragma unroll
                for (int bi = 0; bi < 3; bi++) {
                    uint32_t bfr[8][2];
#pragma unroll
                    for (int nt = 0; nt < 4; nt++) {
                        uint32_t adr = st + BOFF(bi) + boff[nt] +
                                       (((kg0 + kaB) ^ sBx[nt]) << 4);
                        uint32_t r0, r1, r2, r3;
                        LDSM_X4(r0, r1, r2, r3, adr);
                        bfr[2 * nt][0] = r0; bfr[2 * nt][1] = r1;
                        bfr[2 * nt + 1][0] = r2; bfr[2 * nt + 1][1] = r3;
                    }
                    const int na = (bi == 0) ? 3 : ((bi == 1) ? 2 : 1);
#pragma unroll
                    for (int ai = 0; ai < na; ai++) {
                        uint32_t afr[4][4];
#pragma unroll
                        for (int mi = 0; mi < 4; mi++) {
                            uint32_t adr = st + AOFF(ai) + aoff[mi] +
                                           (((kg0 + kaA) ^ sAx[mi]) << 4);
                            LDSM_X4(afr[mi][0], afr[mi][1], afr[mi][2],
                                    afr[mi][3], adr);
                        }
#pragma unroll
                        for (int mi = 0; mi < 4; mi++)
#pragma unroll
                            for (int ni = 0; ni < 8; ni++)
                                MMA16816(acc[mi][ni], afr[mi], bfr[ni]);
                    }
                }
            }
            __syncthreads();
        }

        // ---- epilogue for this row-block ----
#pragma unroll
        for (int mi = 0; mi < 4; mi++)
#pragma unroll
            for (int half = 0; half < 2; half++) {
                const int r = trow0 + wm * 64 + mi * 16 + (l >> 2) + half * 8;
                const float rv = rs[r];
                float best = -1.f; int bc = 0;
#pragma unroll
                for (int ni = 0; ni < 8; ni++)
#pragma unroll
                    for (int e = 0; e < 2; e++) {
                        const int c = wn * 64 + ni * 8 + 2 * (l & 3) + e;
                        float v = acc[mi][ni][half * 2 + e] * rv * cs[c];
                        if (v < SIM_THR) v = 0.f;
                        acc[mi][ni][half * 2 + e] = v;
                        if (v > best) { best = v; bc = c; }
                    }
#pragma unroll
                for (int off = 1; off <= 2; off <<= 1) {
                    float ov = __shfl_xor_sync(0xffffffffu, best, off);
                    int   oc = __shfl_xor_sync(0xffffffffu, bc, off);
                    if (ov > best || (ov == best && oc < bc)) { best = ov; bc = oc; }
                }
                if ((l & 3) == 0)
                    atomicMax(&rowmax[r],
                        ((unsigned long long)__float_as_uint(best) << 32) |
                        (unsigned)(65535 - bc));
            }
        // column maxima
#pragma unroll
        for (int ni = 0; ni < 8; ni++)
#pragma unroll
            for (int e = 0; e < 2; e++) {
                unsigned long long key = 0ull;
#pragma unroll
                for (int mi = 0; mi < 4; mi++)
#pragma unroll
                    for (int half = 0; half < 2; half++) {
                        const int r = trow0 + wm * 64 + mi * 16 + (l >> 2) + half * 8;
                        unsigned long long k2 =
                            ((unsigned long long)__float_as_uint(
                                acc[mi][ni][half * 2 + e]) << 32) |
                            (unsigned)(65535 - r);
                        if (k2 > key) key = k2;
                    }
#pragma unroll
                for (int off = 4; off <= 16; off <<= 1) {
                    unsigned long long o = __shfl_xor_sync(0xffffffffu, key, off);
                    if (o > key) key = o;
                }
                if (l < 4)
                    atomicMax(&colmax[wn * 64 + ni * 8 + 2 * l + e], key);
            }
        __syncthreads();
    }

    // ---- post phase: cycle consistency + masks, one thread per t ----
    {
        int t = tid;
        unsigned long long rm = rowmax[t];
        float st = __uint_as_float((unsigned)(rm >> 32));
        int   it = 65535 - (int)(unsigned)(rm & 0xFFFFFFFFull);
        unsigned long long cm_t  = colmax[t];
        unsigned long long cm_it = colmax[it];
        int idx_s2t_t = 65535 - (int)(unsigned)(cm_t & 0xFFFFFFFFull);
        float sc_s2t  = __uint_as_float((unsigned)(cm_it >> 32));
        int idx_s2s   = 65535 - (int)(unsigned)(cm_it & 0xFFFFFFFFull);

        bool msim = (st >= SIM_THR);
        int dx = (idx_s2s & 15) - (t & 15);
        int dy = (idx_s2s >> 4) - (t >> 4);
        bool mcyc = (dx * dx + dy * dy <= 4) && (sc_s2t >= SIM_THR);

        float mall = 0.f;
        if (msim && mcyc) {
            float mt2s = srcm[bn * T_ + it];
            float tm   = tarm[b * T_ + t];
            mall = tm * mt2s * ((idx_s2t_t != 0) ? 1.f : 0.f)
                             * ((it != 0) ? 1.f : 0.f);
        }
        g_maskall[bn * T_ + t] = mall;
        g_scoret[bn * T_ + t]  = st;
        g_idxt[bn * T_ + t]    = it;

        float s1 = mall, s2 = st * mall;
#pragma unroll
        for (int off = 16; off; off >>= 1) {
            s1 += __shfl_xor_sync(0xffffffffu, s1, off);
            s2 += __shfl_xor_sync(0xffffffffu, s2, off);
        }
        if (l == 0) { wsum1[w] = s1; wsum2[w] = s2; }
        __syncthreads();
        if (tid == 0) {
            float mc = 0.f, ss = 0.f;
            for (int wi = 0; wi < 8; wi++) { mc += wsum1[wi]; ss += wsum2[wi]; }
            g_mc[bn]  = mc;
            g_avg[bn] = (mc > 0.f) ? ss / (float)T_ : 0.f;
        }
    }
}

// ---------------------------------------------------------------------------
// Kernel 3: per-batch top-5 (stable) + output formatting
// ---------------------------------------------------------------------------
__global__ void finalize_kernel(float* __restrict__ out) {
    int b = blockIdx.x;
    int tid = threadIdx.x;
    __shared__ int   sid[K_TOP];
    __shared__ float sval[K_TOP];

    if (tid == 0) {
        bool used[N_];
        for (int n = 0; n < N_; n++) used[n] = false;
        for (int k = 0; k < K_TOP; k++) {
            float best = -1.f; int bi = 0; bool found = false;
            for (int n = 0; n < N_; n++) {
                float v = g_avg[b * N_ + n];
                if (!used[n] && (!found || v > best)) {
                    best = v; bi = n; found = true;
                }
            }
            used[bi] = true; sid[k] = bi; sval[k] = best;
        }
    }
    __syncthreads();

    if (tid < K_TOP) {
        out[b * K_TOP + tid] = (float)sid[tid];
        out[B_ * K_TOP + b * K_TOP + tid] = sval[tid];
    }

    const int OFF_SP   = 2 * B_ * K_TOP;
    const int OFF_TP   = OFF_SP + B_ * K_TOP * T_;
    const int OFF_SRCP = OFF_TP + B_ * K_TOP * T_ * 2;
    const int OFF_MC   = OFF_SRCP + B_ * K_TOP * T_ * 2;

    int t = tid;
#pragma unroll
    for (int k = 0; k < K_TOP; k++) {
        int bnsel = b * N_ + sid[k];
        float sc = g_scoret[bnsel * T_ + t];
        float m  = g_maskall[bnsel * T_ + t];
        int   it = g_idxt[bnsel * T_ + t];
        int base = (b * K_TOP + k) * T_ + t;
        out[OFF_SP + base] = sc;
        bool nz = (m != 0.f);
        out[OFF_TP + base * 2 + 0]   = nz ? (float)(t & 15)  : -1.f;
        out[OFF_TP + base * 2 + 1]   = nz ? (float)(t >> 4)  : -1.f;
        out[OFF_SRCP + base * 2 + 0] = nz ? (float)(it & 15) : -1.f;
        out[OFF_SRCP + base * 2 + 1] = nz ? (float)(it >> 4) : -1.f;
    }
    if (tid < N_) out[OFF_MC + b * N_ + tid] = g_mc[b * N_ + tid];
}

// ---------------------------------------------------------------------------
extern "C" void kernel_launch(void* const* d_in, const int* in_sizes, int n_in,
                              void* d_out, int out_size) {
    const float* sf   = (const float*)d_in[0];  // (B,N,C,P,P)
    const float* tf   = (const float*)d_in[1];  // (B,C,P,P)
    const float* srcm = (const float*)d_in[2];  // (B,N,P,P)
    const float* tarm = (const float*)d_in[3];  // (B,P,P)

    cudaFuncSetAttribute(sim_hmma_kernel,
                         cudaFuncAttributeMaxDynamicSharedMemorySize, SMEM_DYN);

    dim3 gp(B_ * N_ + B_, T_ / 32);
    prep_kernel<<<gp, 256>>>(sf, tf);
    sim_hmma_kernel<<<B_ * N_, 256, SMEM_DYN>>>(srcm, tarm);
    finalize_kernel<<<B_, 256>>>((float*)d_out);
}